// round 1
// baseline (speedup 1.0000x reference)
#include <cuda_runtime.h>
#include <math.h>

#define MAXN 100000
#define MAXE 1600000
#define HID 256
#define H2  128
#define NPB 64   // nodes per block in dense kernel

// ---------------- scratch (device globals; no allocation allowed) -------------
__device__ __align__(16) float g_deg[MAXN];
__device__ __align__(16) float g_dis[MAXN];
__device__ __align__(16) float g_s1[MAXN * 4];            // aggregated dis*x  (layer1, 4-dim)
__device__ __align__(16) float g_ms[(size_t)MAXN * H2];   // dis[i] * (h1[i] @ W2)
__device__ __align__(16) float g_s2[(size_t)MAXN * H2];   // aggregated ms     (layer2, 128-dim)
__device__ float g_sum[H2];

__device__ __forceinline__ void red_add_v4(float* p, float a, float b, float c, float d) {
    asm volatile("red.global.add.v4.f32 [%0], {%1,%2,%3,%4};"
                 :: "l"(p), "f"(a), "f"(b), "f"(c), "f"(d) : "memory");
}

// ---------------- kernels ----------------------------------------------------

// deg init to 1 (self-loop) + zero g_sum
__global__ void k_init(int n) {
    int i = blockIdx.x * blockDim.x + threadIdx.x;
    if (i < n)  g_deg[i] = 1.0f;
    if (i < H2) g_sum[i] = 0.0f;
}

// in-degree accumulation over targets (col)
__global__ void k_deg(const int* __restrict__ ei, int E, int n) {
    int e = blockIdx.x * blockDim.x + threadIdx.x;
    if (e >= E) return;
    int c = ei[E + e];
    if ((unsigned)c < (unsigned)n) atomicAdd(&g_deg[c], 1.0f);
}

// dis = 1/sqrt(deg); s1 init = self-loop term dis*x
__global__ void k_dis(const float4* __restrict__ x, int n) {
    int i = blockIdx.x * blockDim.x + threadIdx.x;
    if (i >= n) return;
    float dis = 1.0f / sqrtf(g_deg[i]);
    g_dis[i] = dis;
    float4 xv = x[i];
    ((float4*)g_s1)[i] = make_float4(dis * xv.x, dis * xv.y, dis * xv.z, dis * xv.w);
}

// layer-1 edge aggregation in 4-dim input space: s1[col] += dis[row]*x[row]
__global__ void k_agg1(const int* __restrict__ ei, const float4* __restrict__ x, int E, int n) {
    int e = blockIdx.x * blockDim.x + threadIdx.x;
    if (e >= E) return;
    int r = ei[e], c = ei[E + e];
    if ((unsigned)r >= (unsigned)n || (unsigned)c >= (unsigned)n) return;
    float dr = g_dis[r];
    float4 xv = x[r];
    red_add_v4(&g_s1[c * 4], dr * xv.x, dr * xv.y, dr * xv.z, dr * xv.w);
}

// fused per-node dense compute:
//   agg1 = dis*s1  ->  h1 = relu(agg1@W1+b1)  ->  m = h1@W2  ->  ms = dis*m
//   s2 initialized with self-loop term (= ms)
__global__ void __launch_bounds__(256, 1)
k_dense(const float* __restrict__ W1, const float* __restrict__ b1,
        const float* __restrict__ W2, int n) {
    extern __shared__ float sm[];
    float* W2s = sm;                       // [256][128]
    float* h1T = sm + HID * H2;            // [256][64]  (k-major, node minor)
    float* a1  = h1T + HID * NPB;          // [4][64]
    int t  = threadIdx.x;                  // 0..255
    int nb = blockIdx.x * NPB;

    for (int i = t; i < HID * H2; i += 256) W2s[i] = W2[i];
    {
        int nn = t >> 2, d = t & 3;
        int gn = nb + nn;
        float v = 0.0f;
        if (gn < n) v = g_dis[gn] * g_s1[gn * 4 + d];
        a1[d * NPB + nn] = v;
    }
    __syncthreads();

    // h1T[k][nn] = relu(sum_d a1[d][nn]*W1[d][k] + b1[k])
    for (int i = t; i < HID * NPB; i += 256) {
        int nn = i & (NPB - 1);
        int k  = i >> 6;
        float acc = b1[k];
        acc = fmaf(a1[nn],           W1[k],           acc);
        acc = fmaf(a1[NPB + nn],     W1[HID + k],     acc);
        acc = fmaf(a1[2 * NPB + nn], W1[2 * HID + k], acc);
        acc = fmaf(a1[3 * NPB + nn], W1[3 * HID + k], acc);
        h1T[k * NPB + nn] = fmaxf(acc, 0.0f);
    }
    __syncthreads();

    // GEMM: C[64x128] = h1[64x256] @ W2[256x128], 4x8 register tile per thread
    int tn = t & 15, tj = t >> 4;
    int n0 = tn * 4, j0 = tj * 8;
    float acc[4][8];
    #pragma unroll
    for (int a = 0; a < 4; a++)
        #pragma unroll
        for (int b = 0; b < 8; b++) acc[a][b] = 0.0f;

    #pragma unroll 4
    for (int k = 0; k < HID; ++k) {
        float4 h  = *(const float4*)&h1T[k * NPB + n0];
        float4 w0 = *(const float4*)&W2s[k * H2 + j0];
        float4 w1 = *(const float4*)&W2s[k * H2 + j0 + 4];
        float hv[4] = {h.x, h.y, h.z, h.w};
        float wv[8] = {w0.x, w0.y, w0.z, w0.w, w1.x, w1.y, w1.z, w1.w};
        #pragma unroll
        for (int a = 0; a < 4; a++)
            #pragma unroll
            for (int b = 0; b < 8; b++)
                acc[a][b] = fmaf(hv[a], wv[b], acc[a][b]);
    }

    #pragma unroll
    for (int a = 0; a < 4; a++) {
        int gn = nb + n0 + a;
        if (gn >= n) break;
        float dn = g_dis[gn];
        float4 v0 = make_float4(acc[a][0] * dn, acc[a][1] * dn, acc[a][2] * dn, acc[a][3] * dn);
        float4 v1 = make_float4(acc[a][4] * dn, acc[a][5] * dn, acc[a][6] * dn, acc[a][7] * dn);
        size_t base = (size_t)gn * H2 + j0;
        *(float4*)&g_ms[base]     = v0;
        *(float4*)&g_ms[base + 4] = v1;
        *(float4*)&g_s2[base]     = v0;   // self-loop init
        *(float4*)&g_s2[base + 4] = v1;
    }
}

// layer-2 edge aggregation: warp per edge, lane handles 4 dims (v4 RED)
__global__ void k_agg2(const int* __restrict__ ei, int E, int n) {
    int idx  = blockIdx.x * blockDim.x + threadIdx.x;
    int e    = idx >> 5;
    if (e >= E) return;
    int lane = idx & 31;
    int r = ei[e], c = ei[E + e];
    if ((unsigned)r >= (unsigned)n || (unsigned)c >= (unsigned)n) return;
    float4 v = ((const float4*)&g_ms[(size_t)r * H2])[lane];
    red_add_v4(&g_s2[(size_t)c * H2 + (size_t)lane * 4], v.x, v.y, v.z, v.w);
}

// mean-pool of relu(dis*s2 + b2): per-dim partial sums -> g_sum
__global__ void k_final(const float* __restrict__ b2, int n) {
    int j = threadIdx.x;   // 128 threads
    float bj  = b2[j];
    float acc = 0.0f;
    for (int i = blockIdx.x; i < n; i += gridDim.x) {
        float v = fmaf(g_dis[i], g_s2[(size_t)i * H2 + j], bj);
        acc += fmaxf(v, 0.0f);
    }
    atomicAdd(&g_sum[j], acc);
}

// final linear head + sigmoid -> single scalar
__global__ void k_head(const float* __restrict__ Wl, const float* __restrict__ bl,
                       float* __restrict__ out, float invN) {
    int j = threadIdx.x;   // 128 threads
    __shared__ float red[H2];
    red[j] = g_sum[j] * invN * Wl[j];
    __syncthreads();
    #pragma unroll
    for (int s = 64; s > 0; s >>= 1) {
        if (j < s) red[j] += red[j + s];
        __syncthreads();
    }
    if (j == 0) out[0] = 1.0f / (1.0f + expf(-(red[0] + bl[0])));
}

// ---------------- launch ------------------------------------------------------
extern "C" void kernel_launch(void* const* d_in, const int* in_sizes, int n_in,
                              void* d_out, int out_size) {
    const float* x  = (const float*)d_in[0];
    const int*   ei = (const int*)d_in[1];   // edge_index (JAX canonicalizes int64->int32)
    const float* W1 = (const float*)d_in[2];
    const float* b1 = (const float*)d_in[3];
    const float* W2 = (const float*)d_in[4];
    const float* b2 = (const float*)d_in[5];
    const float* Wl = (const float*)d_in[6];
    const float* bl = (const float*)d_in[7];
    float* out = (float*)d_out;

    int N = in_sizes[0] / 4;
    int E = in_sizes[1] / 2;

    size_t smem = (size_t)(HID * H2 + HID * NPB + 4 * NPB) * sizeof(float);  // ~193 KB
    cudaFuncSetAttribute(k_dense, cudaFuncAttributeMaxDynamicSharedMemorySize, (int)smem);

    int nbN = (N + 255) / 256;
    int nbE = (E + 255) / 256;

    k_init <<<nbN, 256>>>(N);
    k_deg  <<<nbE, 256>>>(ei, E, N);
    k_dis  <<<nbN, 256>>>((const float4*)x, N);
    k_agg1 <<<nbE, 256>>>(ei, (const float4*)x, E, N);
    k_dense<<<(N + NPB - 1) / NPB, 256, smem>>>(W1, b1, W2, N);
    k_agg2 <<<(E + 7) / 8, 256>>>(ei, E, N);
    k_final<<<1024, H2>>>(b2, N);
    k_head <<<1, H2>>>(Wl, bl, out, 1.0f / (float)N);
}

// round 2
// speedup vs baseline: 2.6637x; 2.6637x over previous
#include <cuda_runtime.h>
#include <cuda_bf16.h>
#include <math.h>

#define MAXN 100000
#define MAXE 1600000
#define HID 256
#define H2  128
#define NPB 128           // nodes per block in dense kernel
#define LDA 264           // h1 smem row stride (bf16), padded
#define LDB 136           // W2 row stride (bf16), padded

// ---------------- scratch (device globals; no allocation allowed) -------------
__device__ __align__(16) int   g_cnt[MAXN];
__device__ __align__(16) int   g_off[MAXN];
__device__ __align__(16) int   g_cur[MAXN];
__device__ __align__(16) int   g_src[MAXE];
__device__ __align__(16) int   g_bsum[1024];
__device__ __align__(16) int   g_bbase[1024];
__device__ __align__(16) float g_dis[MAXN];
__device__ __align__(16) float g_a1[MAXN * 4];                 // dis*(aggregated dis*x)
__device__ __align__(16) __nv_bfloat16 g_W2b[HID * LDB];       // padded bf16 W2
__device__ __align__(16) __nv_bfloat16 g_ms[(size_t)MAXN * H2];// dis * (h1 @ W2), bf16
__device__ float g_sum[H2];

__device__ __forceinline__ void red_add_v4(float* p, float a, float b, float c, float d) {
    asm volatile("red.global.add.v4.f32 [%0], {%1,%2,%3,%4};"
                 :: "l"(p), "f"(a), "f"(b), "f"(c), "f"(d) : "memory");
}

// ---------------- CSR build --------------------------------------------------
__global__ void k_init(int n) {
    int i = blockIdx.x * blockDim.x + threadIdx.x;
    if (i < n) { g_cnt[i] = 0; g_cur[i] = 0; }
    if (i < H2) g_sum[i] = 0.0f;
}

__global__ void k_hist(const int* __restrict__ ei, int E, int n) {
    int e = blockIdx.x * blockDim.x + threadIdx.x;
    if (e >= E) return;
    int c = ei[E + e];
    if ((unsigned)c < (unsigned)n) atomicAdd(&g_cnt[c], 1);
}

// block-level exclusive scan over g_cnt, also produce dis = rsqrt(1+cnt)
__global__ void k_scan1(int n) {
    __shared__ int s[1024];
    int t = threadIdx.x;
    int gid = blockIdx.x * 1024 + t;
    int v = (gid < n) ? g_cnt[gid] : 0;
    s[t] = v;
    __syncthreads();
    for (int o = 1; o < 1024; o <<= 1) {
        int u = (t >= o) ? s[t - o] : 0;
        __syncthreads();
        s[t] += u;
        __syncthreads();
    }
    if (gid < n) {
        g_off[gid] = s[t] - v;                 // exclusive within block
        g_dis[gid] = rsqrtf(1.0f + (float)v);
    }
    if (t == 1023) g_bsum[blockIdx.x] = s[1023];
}

__global__ void k_scan2(int nb) {
    __shared__ int s[1024];
    int t = threadIdx.x;
    int v = (t < nb) ? g_bsum[t] : 0;
    s[t] = v;
    __syncthreads();
    for (int o = 1; o < 1024; o <<= 1) {
        int u = (t >= o) ? s[t - o] : 0;
        __syncthreads();
        s[t] += u;
        __syncthreads();
    }
    if (t < nb) g_bbase[t] = s[t] - v;
}

__global__ void k_scan3(int n) {
    int gid = blockIdx.x * 1024 + threadIdx.x;
    if (gid < n) g_off[gid] += g_bbase[blockIdx.x];
}

__global__ void k_scatter(const int* __restrict__ ei, int E, int n) {
    int e = blockIdx.x * blockDim.x + threadIdx.x;
    if (e >= E) return;
    int r = ei[e], c = ei[E + e];
    if ((unsigned)r >= (unsigned)n || (unsigned)c >= (unsigned)n) return;
    int p = g_off[c] + atomicAdd(&g_cur[c], 1);
    g_src[p] = r;
}

// ---------------- layer-1 gather aggregation (4-dim) --------------------------
__global__ void k_agg1g(const float4* __restrict__ x, int n) {
    int i = blockIdx.x * blockDim.x + threadIdx.x;
    if (i >= n) return;
    float dc = g_dis[i];
    float4 xi = x[i];
    float ax = dc * xi.x, ay = dc * xi.y, az = dc * xi.z, aw = dc * xi.w; // self
    int off = g_off[i], cnt = g_cnt[i];
    #pragma unroll 2
    for (int e = 0; e < cnt; ++e) {
        int r = g_src[off + e];
        float dr = g_dis[r];
        float4 xr = x[r];
        ax = fmaf(dr, xr.x, ax);
        ay = fmaf(dr, xr.y, ay);
        az = fmaf(dr, xr.z, az);
        aw = fmaf(dr, xr.w, aw);
    }
    ((float4*)g_a1)[i] = make_float4(dc * ax, dc * ay, dc * az, dc * aw);
}

// ---------------- W2 -> padded bf16 ------------------------------------------
__global__ void k_prep(const float* __restrict__ W2) {
    int i = blockIdx.x * blockDim.x + threadIdx.x;   // 0..HID*H2-1
    if (i >= HID * H2) return;
    int k = i / H2, nn = i % H2;
    g_W2b[k * LDB + nn] = __float2bfloat16(W2[i]);
}

// ---------------- fused dense: h1 = relu(a1@W1+b1); ms = dis*(h1@W2) ----------
__global__ void __launch_bounds__(256, 1)
k_dense2(const float* __restrict__ W1, const float* __restrict__ b1, int n) {
    extern __shared__ __nv_bfloat16 sm[];
    __nv_bfloat16* W2s = sm;                 // [HID][LDB]
    __nv_bfloat16* h1s = sm + HID * LDB;     // [NPB][LDA]
    int t = threadIdx.x;
    int nb = blockIdx.x * NPB;

    // copy padded bf16 W2 into smem (16B vectors)
    {
        const uint4* src = (const uint4*)g_W2b;
        uint4* dst = (uint4*)W2s;
        for (int i = t; i < HID * LDB / 8; i += 256) dst[i] = src[i];
    }

    // compute h1 (bf16) : thread t handles node t>>1, k-half (t&1)*128
    {
        int nn = t >> 1;
        int kh = (t & 1) << 7;
        int gn = nb + nn;
        float4 a = make_float4(0.f, 0.f, 0.f, 0.f);
        if (gn < n) a = ((const float4*)g_a1)[gn];
        for (int k = kh; k < kh + 128; k += 2) {
            float v0 = b1[k];
            v0 = fmaf(a.x, W1[k],           v0);
            v0 = fmaf(a.y, W1[HID + k],     v0);
            v0 = fmaf(a.z, W1[2 * HID + k], v0);
            v0 = fmaf(a.w, W1[3 * HID + k], v0);
            float v1 = b1[k + 1];
            v1 = fmaf(a.x, W1[k + 1],           v1);
            v1 = fmaf(a.y, W1[HID + k + 1],     v1);
            v1 = fmaf(a.z, W1[2 * HID + k + 1], v1);
            v1 = fmaf(a.w, W1[3 * HID + k + 1], v1);
            v0 = fmaxf(v0, 0.0f);
            v1 = fmaxf(v1, 0.0f);
            *(__nv_bfloat162*)&h1s[nn * LDA + k] =
                __floats2bfloat162_rn(v0, v1);
        }
    }
    __syncthreads();

    // tensor-core GEMM: 8 warps, warp w -> rows [16w,16w+16), all 128 cols
    int w = t >> 5, lane = t & 31;
    int m0 = w * 16;
    float c[16][4];
    #pragma unroll
    for (int nt = 0; nt < 16; nt++)
        #pragma unroll
        for (int q = 0; q < 4; q++) c[nt][q] = 0.0f;

    // per-lane ldmatrix base addresses
    unsigned a_base = (unsigned)__cvta_generic_to_shared(
        &h1s[(m0 + (lane & 15)) * LDA + ((lane >> 4) << 3)]);
    unsigned b_row = (unsigned)__cvta_generic_to_shared(
        &W2s[(lane & 15) * LDB]);

    for (int kk = 0; kk < 16; ++kk) {
        unsigned a0, a1r, a2, a3;
        asm volatile("ldmatrix.sync.aligned.m8n8.x4.shared.b16 {%0,%1,%2,%3},[%4];"
                     : "=r"(a0), "=r"(a1r), "=r"(a2), "=r"(a3)
                     : "r"(a_base + kk * 16 * 2));
        unsigned b_k = b_row + kk * 16 * LDB * 2;
        #pragma unroll
        for (int nt = 0; nt < 16; ++nt) {
            unsigned b0, b1r;
            asm volatile("ldmatrix.sync.aligned.m8n8.x2.trans.shared.b16 {%0,%1},[%2];"
                         : "=r"(b0), "=r"(b1r)
                         : "r"(b_k + nt * 8 * 2));
            asm volatile("mma.sync.aligned.m16n8k16.row.col.f32.bf16.bf16.f32 "
                         "{%0,%1,%2,%3},{%4,%5,%6,%7},{%8,%9},{%0,%1,%2,%3};"
                         : "+f"(c[nt][0]), "+f"(c[nt][1]), "+f"(c[nt][2]), "+f"(c[nt][3])
                         : "r"(a0), "r"(a1r), "r"(a2), "r"(a3), "r"(b0), "r"(b1r));
        }
    }

    // epilogue: scale by dis, store bf16 rows of g_ms
    int gn0 = nb + m0 + (lane >> 2);
    int gn1 = gn0 + 8;
    float d0 = (gn0 < n) ? g_dis[gn0] : 0.0f;
    float d1 = (gn1 < n) ? g_dis[gn1] : 0.0f;
    #pragma unroll
    for (int nt = 0; nt < 16; ++nt) {
        int col = nt * 8 + ((lane & 3) << 1);
        if (gn0 < n)
            *(__nv_bfloat162*)&g_ms[(size_t)gn0 * H2 + col] =
                __floats2bfloat162_rn(c[nt][0] * d0, c[nt][1] * d0);
        if (gn1 < n)
            *(__nv_bfloat162*)&g_ms[(size_t)gn1 * H2 + col] =
                __floats2bfloat162_rn(c[nt][2] * d1, c[nt][3] * d1);
    }
}

// ---------------- layer-2 gather agg + relu + b2 + mean-pool ------------------
__global__ void k_agg2f(const float* __restrict__ b2, int n, int totWarps) {
    int wid = (blockIdx.x * blockDim.x + threadIdx.x) >> 5;
    int lane = threadIdx.x & 31;
    float4 bv = ((const float4*)b2)[lane];
    float s0 = 0.f, s1 = 0.f, s2 = 0.f, s3 = 0.f;
    const uint2* msv = (const uint2*)g_ms;   // 8B = 4 bf16 per lane

    for (int cnode = wid; cnode < n; cnode += totWarps) {
        // self term
        uint2 mv = msv[(size_t)cnode * 32 + lane];
        __nv_bfloat162 p0 = *(__nv_bfloat162*)&mv.x;
        __nv_bfloat162 p1 = *(__nv_bfloat162*)&mv.y;
        float2 f0 = __bfloat1622float2(p0);
        float2 f1 = __bfloat1622float2(p1);
        float a0 = f0.x, a1 = f0.y, a2 = f1.x, a3 = f1.y;

        int off = g_off[cnode], cnt = g_cnt[cnode];
        for (int base = 0; base < cnt; base += 32) {
            int si = (base + lane < cnt) ? g_src[off + base + lane] : 0;
            int m = min(32, cnt - base);
            #pragma unroll 4
            for (int k = 0; k < m; ++k) {
                int r = __shfl_sync(0xffffffffu, si, k);
                uint2 v = msv[(size_t)r * 32 + lane];
                __nv_bfloat162 q0 = *(__nv_bfloat162*)&v.x;
                __nv_bfloat162 q1 = *(__nv_bfloat162*)&v.y;
                float2 g0 = __bfloat1622float2(q0);
                float2 g1 = __bfloat1622float2(q1);
                a0 += g0.x; a1 += g0.y; a2 += g1.x; a3 += g1.y;
            }
        }
        float dc = g_dis[cnode];
        s0 += fmaxf(fmaf(dc, a0, bv.x), 0.0f);
        s1 += fmaxf(fmaf(dc, a1, bv.y), 0.0f);
        s2 += fmaxf(fmaf(dc, a2, bv.z), 0.0f);
        s3 += fmaxf(fmaf(dc, a3, bv.w), 0.0f);
    }
    red_add_v4(&g_sum[lane * 4], s0, s1, s2, s3);
}

// ---------------- head --------------------------------------------------------
__global__ void k_head(const float* __restrict__ Wl, const float* __restrict__ bl,
                       float* __restrict__ out, float invN) {
    int j = threadIdx.x;   // 128 threads
    __shared__ float red[H2];
    red[j] = g_sum[j] * invN * Wl[j];
    __syncthreads();
    #pragma unroll
    for (int s = 64; s > 0; s >>= 1) {
        if (j < s) red[j] += red[j + s];
        __syncthreads();
    }
    if (j == 0) out[0] = 1.0f / (1.0f + expf(-(red[0] + bl[0])));
}

// ---------------- launch ------------------------------------------------------
extern "C" void kernel_launch(void* const* d_in, const int* in_sizes, int n_in,
                              void* d_out, int out_size) {
    const float* x  = (const float*)d_in[0];
    const int*   ei = (const int*)d_in[1];
    const float* W1 = (const float*)d_in[2];
    const float* b1 = (const float*)d_in[3];
    const float* W2 = (const float*)d_in[4];
    const float* b2 = (const float*)d_in[5];
    const float* Wl = (const float*)d_in[6];
    const float* bl = (const float*)d_in[7];
    float* out = (float*)d_out;

    int N = in_sizes[0] / 4;
    int E = in_sizes[1] / 2;

    size_t smem = (size_t)(HID * LDB + NPB * LDA) * sizeof(__nv_bfloat16);
    cudaFuncSetAttribute(k_dense2, cudaFuncAttributeMaxDynamicSharedMemorySize, (int)smem);

    int nbN  = (N + 255) / 256;
    int nbE  = (E + 255) / 256;
    int nbS  = (N + 1023) / 1024;

    k_init   <<<nbN, 256>>>(N);
    k_hist   <<<nbE, 256>>>(ei, E, N);
    k_scan1  <<<nbS, 1024>>>(N);
    k_scan2  <<<1, 1024>>>(nbS);
    k_scan3  <<<nbS, 1024>>>(N);
    k_scatter<<<nbE, 256>>>(ei, E, N);
    k_prep   <<<(HID * H2 + 255) / 256, 256>>>(W2);
    k_agg1g  <<<nbN, 256>>>((const float4*)x, N);
    k_dense2 <<<(N + NPB - 1) / NPB, 256, smem>>>(W1, b1, N);
    int blocksA = 592;                         // 4736 warps
    k_agg2f  <<<blocksA, 256>>>(b2, N, blocksA * 8);
    k_head   <<<1, H2>>>(Wl, bl, out, 1.0f / (float)N);
}